// round 2
// baseline (speedup 1.0000x reference)
#include <cuda_runtime.h>
#include <cstddef>

#define D 64
#define MAXN 100000

// Scratch buffers (no allocation allowed) -----------------------------------
__device__ float g_A[MAXN * D];
__device__ float g_B[MAXN * D];
__device__ float g_C[MAXN * D];
__device__ float g_AG[MAXN * D];

// ---------------------------------------------------------------------------
__global__ __launch_bounds__(512) void zero_kernel(float* __restrict__ p, int n) {
    int i = blockIdx.x * blockDim.x + threadIdx.x;
    if (i < n) p[i] = 0.0f;
}

// out[i,:] = in[idx[i],:]
__global__ __launch_bounds__(512) void gather_kernel(const float* __restrict__ in,
                                                     const int* __restrict__ idx,
                                                     float* __restrict__ out, int n) {
    int i = blockIdx.x * blockDim.x + threadIdx.x;
    if (i < n * D) {
        int row = i >> 6;
        int col = i & 63;
        out[i] = in[(size_t)idx[row] * D + col];
    }
}

// encode: x[n,16] -> relu(x@W1+b1)@W2+b2 -> out[n,64]
__global__ __launch_bounds__(512) void encode_kernel(const float* __restrict__ x,
                                                     const float* __restrict__ W1,
                                                     const float* __restrict__ b1,
                                                     const float* __restrict__ W2,
                                                     const float* __restrict__ b2,
                                                     float* __restrict__ out, int n) {
    __shared__ __align__(16) float W1s[16 * D];
    __shared__ __align__(16) float W2s[D * D];
    __shared__ __align__(16) float b1s[D];
    __shared__ __align__(16) float b2s[D];
    __shared__ __align__(16) float inb[8][16];
    __shared__ __align__(16) float yb[8][D];
    int t = threadIdx.x;
    for (int i = t; i < 16 * D; i += 512) W1s[i] = W1[i];
    for (int i = t; i < D * D; i += 512) W2s[i] = W2[i];
    if (t < D) { b1s[t] = b1[t]; b2s[t] = b2[t]; }
    __syncthreads();
    int g = t >> 6, j = t & 63;
    for (long base = (long)blockIdx.x * 8; base < n; base += (long)gridDim.x * 8) {
        int node = (int)base + g;
        bool valid = node < n;
        if (valid && j < 16) inb[g][j] = x[(size_t)node * 16 + j];
        __syncthreads();
        if (valid) {
            float acc = b1s[j];
#pragma unroll
            for (int k = 0; k < 16; k++) acc += inb[g][k] * W1s[k * D + j];
            yb[g][j] = fmaxf(acc, 0.0f);
        }
        __syncthreads();
        if (valid) {
            float acc = b2s[j];
            const float4* y4 = (const float4*)&yb[g][0];
#pragma unroll
            for (int kk = 0; kk < 16; kk++) {
                float4 v = y4[kk];
                int k = kk * 4;
                acc += v.x * W2s[(k + 0) * D + j];
                acc += v.y * W2s[(k + 1) * D + j];
                acc += v.z * W2s[(k + 2) * D + j];
                acc += v.w * W2s[(k + 3) * D + j];
            }
            out[(size_t)node * D + j] = acc;
        }
        __syncthreads();
    }
}

// edge MLP + scatter-add: aggr[r[e]] += relu(h[s[e]]@W1+b1)@W2+b2
__global__ __launch_bounds__(512) void edge_mp_kernel(const float* __restrict__ hin,
                                                      const int* __restrict__ s,
                                                      const int* __restrict__ r,
                                                      const float* __restrict__ W1,
                                                      const float* __restrict__ b1,
                                                      const float* __restrict__ W2,
                                                      const float* __restrict__ b2,
                                                      float* __restrict__ aggr, int E) {
    __shared__ __align__(16) float W1s[D * D];
    __shared__ __align__(16) float W2s[D * D];
    __shared__ __align__(16) float b1s[D];
    __shared__ __align__(16) float b2s[D];
    __shared__ __align__(16) float hbuf[8][D];
    __shared__ __align__(16) float ybuf[8][D];
    int t = threadIdx.x;
    for (int i = t; i < D * D; i += 512) { W1s[i] = W1[i]; W2s[i] = W2[i]; }
    if (t < D) { b1s[t] = b1[t]; b2s[t] = b2[t]; }
    __syncthreads();
    int g = t >> 6, j = t & 63;
    for (long base = (long)blockIdx.x * 8; base < E; base += (long)gridDim.x * 8) {
        int e = (int)base + g;
        bool valid = e < E;
        if (valid) {
            int sidx = s[e];
            hbuf[g][j] = hin[(size_t)sidx * D + j];
        }
        __syncthreads();
        if (valid) {
            float acc = b1s[j];
            const float4* h4 = (const float4*)&hbuf[g][0];
#pragma unroll
            for (int kk = 0; kk < 16; kk++) {
                float4 v = h4[kk];
                int k = kk * 4;
                acc += v.x * W1s[(k + 0) * D + j];
                acc += v.y * W1s[(k + 1) * D + j];
                acc += v.z * W1s[(k + 2) * D + j];
                acc += v.w * W1s[(k + 3) * D + j];
            }
            ybuf[g][j] = fmaxf(acc, 0.0f);
        }
        __syncthreads();
        if (valid) {
            float acc = b2s[j];
            const float4* y4 = (const float4*)&ybuf[g][0];
#pragma unroll
            for (int kk = 0; kk < 16; kk++) {
                float4 v = y4[kk];
                int k = kk * 4;
                acc += v.x * W2s[(k + 0) * D + j];
                acc += v.y * W2s[(k + 1) * D + j];
                acc += v.z * W2s[(k + 2) * D + j];
                acc += v.w * W2s[(k + 3) * D + j];
            }
            int ridx = r[e];
            atomicAdd(&aggr[(size_t)ridx * D + j], acc);
        }
        __syncthreads();
    }
}

// node MLP: out = relu([h, aggr]@Wn1+b1)@Wn2+b2 (+ skip)
__global__ __launch_bounds__(512) void node_mp_kernel(const float* __restrict__ hin,
                                                      const float* __restrict__ aggr,
                                                      const float* __restrict__ W1,
                                                      const float* __restrict__ b1,
                                                      const float* __restrict__ W2,
                                                      const float* __restrict__ b2,
                                                      const float* __restrict__ skip,
                                                      float* __restrict__ out, int n) {
    extern __shared__ __align__(16) float sm[];
    float* W1s = sm;                    // 128*64
    float* W2s = W1s + 128 * D;         // 64*64
    float* b1s = W2s + D * D;           // 64
    float* b2s = b1s + D;               // 64
    float* inb = b2s + D;               // 8*128
    float* yb  = inb + 8 * 128;         // 8*64
    int t = threadIdx.x;
    for (int i = t; i < 128 * D; i += 512) W1s[i] = W1[i];
    for (int i = t; i < D * D; i += 512) W2s[i] = W2[i];
    if (t < D) { b1s[t] = b1[t]; b2s[t] = b2[t]; }
    __syncthreads();
    int g = t >> 6, j = t & 63;
    for (long base = (long)blockIdx.x * 8; base < n; base += (long)gridDim.x * 8) {
        // load 8 rows of [h | aggr] (1024 floats by 512 threads)
        for (int i = t; i < 8 * 128; i += 512) {
            int gg = i >> 7, jj = i & 127;
            int node = (int)base + gg;
            if (node < n)
                inb[i] = (jj < D) ? hin[(size_t)node * D + jj]
                                  : aggr[(size_t)node * D + (jj - D)];
        }
        __syncthreads();
        int node = (int)base + g;
        bool valid = node < n;
        if (valid) {
            float acc = b1s[j];
            const float4* h4 = (const float4*)&inb[g * 128];
#pragma unroll
            for (int kk = 0; kk < 32; kk++) {
                float4 v = h4[kk];
                int k = kk * 4;
                acc += v.x * W1s[(k + 0) * D + j];
                acc += v.y * W1s[(k + 1) * D + j];
                acc += v.z * W1s[(k + 2) * D + j];
                acc += v.w * W1s[(k + 3) * D + j];
            }
            yb[g * D + j] = fmaxf(acc, 0.0f);
        }
        __syncthreads();
        if (valid) {
            float acc = b2s[j];
            const float4* y4 = (const float4*)&yb[g * D];
#pragma unroll
            for (int kk = 0; kk < 16; kk++) {
                float4 v = y4[kk];
                int k = kk * 4;
                acc += v.x * W2s[(k + 0) * D + j];
                acc += v.y * W2s[(k + 1) * D + j];
                acc += v.z * W2s[(k + 2) * D + j];
                acc += v.w * W2s[(k + 3) * D + j];
            }
            if (skip) acc += skip[(size_t)node * D + j];
            out[(size_t)node * D + j] = acc;
        }
        __syncthreads();
    }
}

// decode: out[n,2] = relu(h@Wd1+bd1)@Wd2+bd2
__global__ __launch_bounds__(512) void decode_kernel(const float* __restrict__ hin,
                                                     const float* __restrict__ W1,
                                                     const float* __restrict__ b1,
                                                     const float* __restrict__ W2,
                                                     const float* __restrict__ b2,
                                                     float* __restrict__ out, int n) {
    __shared__ __align__(16) float W1s[D * D];
    __shared__ __align__(16) float b1s[D];
    __shared__ __align__(16) float W2s[D * 2];
    __shared__ __align__(16) float b2s[4];
    __shared__ __align__(16) float inb[8][D];
    __shared__ __align__(16) float yb[8][D];
    int t = threadIdx.x;
    for (int i = t; i < D * D; i += 512) W1s[i] = W1[i];
    if (t < D) b1s[t] = b1[t];
    if (t < D * 2) W2s[t] = W2[t];
    if (t < 2) b2s[t] = b2[t];
    __syncthreads();
    int g = t >> 6, j = t & 63;
    for (long base = (long)blockIdx.x * 8; base < n; base += (long)gridDim.x * 8) {
        int node = (int)base + g;
        bool valid = node < n;
        if (valid) inb[g][j] = hin[(size_t)node * D + j];
        __syncthreads();
        if (valid) {
            float acc = b1s[j];
            const float4* h4 = (const float4*)&inb[g][0];
#pragma unroll
            for (int kk = 0; kk < 16; kk++) {
                float4 v = h4[kk];
                int k = kk * 4;
                acc += v.x * W1s[(k + 0) * D + j];
                acc += v.y * W1s[(k + 1) * D + j];
                acc += v.z * W1s[(k + 2) * D + j];
                acc += v.w * W1s[(k + 3) * D + j];
            }
            yb[g][j] = fmaxf(acc, 0.0f);
        }
        __syncthreads();
        if (valid && j < 2) {
            float acc = b2s[j];
#pragma unroll
            for (int k = 0; k < D; k++) acc += yb[g][k] * W2s[k * 2 + j];
            out[(size_t)node * 2 + j] = acc;
        }
        __syncthreads();
    }
}

// ---------------------------------------------------------------------------
static inline int capgrid(int x) { return x > 4096 ? 4096 : (x < 1 ? 1 : x); }

extern "C" void kernel_launch(void* const* d_in, const int* in_sizes, int n_in,
                              void* d_out, int out_size) {
    const float* x   = (const float*)d_in[0];
    const float* We1 = (const float*)d_in[1];
    const float* be1 = (const float*)d_in[2];
    const float* We2 = (const float*)d_in[3];
    const float* be2 = (const float*)d_in[4];
    const float* Wm1 = (const float*)d_in[5];
    const float* bm1 = (const float*)d_in[6];
    const float* Wm2 = (const float*)d_in[7];
    const float* bm2 = (const float*)d_in[8];
    const float* Wn1 = (const float*)d_in[9];
    const float* bn1 = (const float*)d_in[10];
    const float* Wn2 = (const float*)d_in[11];
    const float* bn2 = (const float*)d_in[12];
    const float* Wd1 = (const float*)d_in[13];
    const float* bd1 = (const float*)d_in[14];
    const float* Wd2 = (const float*)d_in[15];
    const float* bd2 = (const float*)d_in[16];
    const int* s_f  = (const int*)d_in[17];
    const int* r_f  = (const int*)d_in[18];
    const int* s_ds = (const int*)d_in[19];
    const int* r_ds = (const int*)d_in[20];
    const int* s_p  = (const int*)d_in[21];
    const int* r_p  = (const int*)d_in[22];
    const int* s_us = (const int*)d_in[23];
    const int* r_us = (const int*)d_in[24];
    const int* uppool   = (const int*)d_in[25];
    const int* downpool = (const int*)d_in[26];

    int N   = in_sizes[0] / 16;
    int NP  = in_sizes[26];
    int E   = in_sizes[17];
    int EDS = in_sizes[19];
    int EP  = in_sizes[21];
    int EUS = in_sizes[23];
    float* out = (float*)d_out;

    float *A, *B, *C, *AG;
    cudaGetSymbolAddress((void**)&A, g_A);
    cudaGetSymbolAddress((void**)&B, g_B);
    cudaGetSymbolAddress((void**)&C, g_C);
    cudaGetSymbolAddress((void**)&AG, g_AG);

    const size_t NODE_SMEM = (size_t)(128 * D + D * D + D + D + 8 * 128 + 8 * D) * sizeof(float);
    cudaFuncSetAttribute(node_mp_kernel, cudaFuncAttributeMaxDynamicSharedMemorySize,
                         (int)NODE_SMEM);

    auto mp = [&](int l, const float* hin, float* hout, const int* s, const int* r,
                  int Ecnt, int n, const float* skip) {
        zero_kernel<<<(n * D + 511) / 512, 512>>>(AG, n * D);
        edge_mp_kernel<<<capgrid((Ecnt + 7) / 8), 512>>>(
            hin, s, r, Wm1 + (size_t)l * D * D, bm1 + (size_t)l * D,
            Wm2 + (size_t)l * D * D, bm2 + (size_t)l * D, AG, Ecnt);
        node_mp_kernel<<<capgrid((n + 7) / 8), 512, NODE_SMEM>>>(
            hin, AG, Wn1 + (size_t)l * 128 * D, bn1 + (size_t)l * D,
            Wn2 + (size_t)l * D * D, bn2 + (size_t)l * D, skip, hout, n);
    };

    // encode
    encode_kernel<<<capgrid((N + 7) / 8), 512>>>(x, We1, be1, We2, be2, A, N);
    // two fine MP layers
    mp(0, A, B, s_f, r_f, E, N, nullptr);
    mp(1, B, C, s_f, r_f, E, N, nullptr);
    // skip = C
    // downsample path: gather by uppool, MP on downsampling graph
    gather_kernel<<<(N * D + 511) / 512, 512>>>(C, uppool, A, N);
    mp(2, A, B, s_ds, r_ds, EDS, N, nullptr);
    // select pooled nodes
    gather_kernel<<<(NP * D + 511) / 512, 512>>>(B, downpool, A, NP);
    // bottleneck
    mp(3, A, B, s_p, r_p, EP, NP, nullptr);
    mp(4, B, A, s_p, r_p, EP, NP, nullptr);
    // upsample path: gather by downpool, MP on upsampling graph
    gather_kernel<<<(NP * D + 511) / 512, 512>>>(A, downpool, B, NP);
    mp(5, B, A, s_us, r_us, EUS, NP, nullptr);
    // scatter back to fine level via uppool gather
    gather_kernel<<<(N * D + 511) / 512, 512>>>(A, uppool, B, N);
    // decode MP layers with skip connections
    mp(6, B, A, s_f, r_f, E, N, C);
    mp(7, A, B, s_f, r_f, E, N, C);
    // decode head
    decode_kernel<<<capgrid((N + 7) / 8), 512>>>(B, Wd1, bd1, Wd2, bd2, out, N);
}

// round 3
// speedup vs baseline: 7.4056x; 7.4056x over previous
#include <cuda_runtime.h>
#include <cstddef>

#define D 64
#define MAXN 100000

// Scratch buffers (no allocation allowed) -----------------------------------
__device__ float g_A[MAXN * D];
__device__ float g_B[MAXN * D];
__device__ float g_C[MAXN * D];
__device__ float g_M[MAXN * D];   // per-node messages
__device__ float g_AG[MAXN * D];  // aggregation

// ---------------------------------------------------------------------------
__global__ __launch_bounds__(512) void zero_kernel(float* __restrict__ p, int n) {
    int i = blockIdx.x * blockDim.x + threadIdx.x;
    if (i < n) p[i] = 0.0f;
}

// out[i,:] = in[idx[i],:]  (row width 64)
__global__ __launch_bounds__(512) void gather_kernel(const float* __restrict__ in,
                                                     const int* __restrict__ idx,
                                                     float* __restrict__ out, int n) {
    int i = blockIdx.x * blockDim.x + threadIdx.x;
    if (i < n * 16) {
        int row = i >> 4;
        int c = i & 15;
        ((float4*)out)[i] = ((const float4*)in)[(size_t)idx[row] * 16 + c];
    }
}

// aggr[r[e],:] += msg[s[e],:]   via red.global.add.v4.f32
__global__ __launch_bounds__(256) void scatter_kernel(const float* __restrict__ msg,
                                                      const int* __restrict__ s,
                                                      const int* __restrict__ r,
                                                      float* __restrict__ aggr, long E16) {
    for (long i = (long)blockIdx.x * 256 + threadIdx.x; i < E16;
         i += (long)gridDim.x * 256) {
        int e = (int)(i >> 4);
        int c = (int)(i & 15);
        int se = __ldg(&s[e]);
        int re = __ldg(&r[e]);
        float4 v = __ldg((const float4*)msg + (size_t)se * 16 + c);
        float* dst = aggr + (size_t)re * 64 + c * 4;
        asm volatile("red.global.add.v4.f32 [%0], {%1,%2,%3,%4};"
                     :: "l"(dst), "f"(v.x), "f"(v.y), "f"(v.z), "f"(v.w)
                     : "memory");
    }
}

// ---------------------------------------------------------------------------
// Generic register-tiled 2-layer MLP:  out = relu(X @ W1 + b1) @ W2 + b2 (+skip)
// X rows: [in0 | in1] concat when IN==128 (both row-width 64), in0 row-width IN
// otherwise. 256 threads; tile = 64 rows x 64 cols; thread tile = 4x4.
// ---------------------------------------------------------------------------
template <int IN>
__global__ __launch_bounds__(256) void mlp2_tiled(const float* __restrict__ in0,
                                                  const float* __restrict__ in1,
                                                  const float* __restrict__ W1,
                                                  const float* __restrict__ b1,
                                                  const float* __restrict__ W2,
                                                  const float* __restrict__ b2,
                                                  const float* __restrict__ skip,
                                                  float* __restrict__ out, int n) {
    extern __shared__ __align__(16) float sm[];
    constexpr int XS = IN + 4;               // padded input row stride (floats)
    float* W1s = sm;                         // IN*64
    float* W2s = W1s + IN * 64;              // 64*64
    float* b1s = W2s + 64 * 64;              // 64
    float* b2s = b1s + 64;                   // 64
    float* inb = b2s + 64;                   // 64*XS
    float* yb  = inb + 64 * XS;              // 64*68

    const int t = threadIdx.x;
    for (int i = t; i < IN * 64; i += 256) W1s[i] = W1[i];
    for (int i = t; i < 64 * 64; i += 256) W2s[i] = W2[i];
    if (t < 64) { b1s[t] = b1[t]; b2s[t] = b2[t]; }
    __syncthreads();

    const int tc = t & 15;        // col group (j = tc*4)
    const int tr = t >> 4;        // row group (rows tr*4 .. tr*4+3)
    const int j = tc * 4;
    const int tiles = (n + 63) >> 6;

    for (int tile = blockIdx.x; tile < tiles; tile += gridDim.x) {
        const int base = tile * 64;
        // ---- stage X tile ----
        constexpr int C4 = IN / 4;
        for (int i = t; i < 64 * C4; i += 256) {
            int row = i / C4, c4 = i % C4, col = c4 * 4;
            int node = base + row;
            float4 v = make_float4(0.f, 0.f, 0.f, 0.f);
            if (node < n) {
                if (IN == 128 && col >= 64)
                    v = *(const float4*)&in1[(size_t)node * 64 + (col - 64)];
                else
                    v = *(const float4*)&in0[(size_t)node * (IN == 128 ? 64 : IN) + col];
            }
            *(float4*)&inb[row * XS + col] = v;
        }
        __syncthreads();

        // ---- GEMM1: Y = relu(X @ W1 + b1) ----
        float acc[4][4];
#pragma unroll
        for (int i = 0; i < 4; i++)
#pragma unroll
            for (int c = 0; c < 4; c++) acc[i][c] = b1s[j + c];
#pragma unroll
        for (int k = 0; k < IN; k += 4) {
            float4 xq[4];
#pragma unroll
            for (int i = 0; i < 4; i++)
                xq[i] = *(const float4*)&inb[(tr * 4 + i) * XS + k];
#pragma unroll
            for (int kk = 0; kk < 4; kk++) {
                float4 w = *(const float4*)&W1s[(k + kk) * 64 + j];
#pragma unroll
                for (int i = 0; i < 4; i++) {
                    float xv = ((const float*)&xq[i])[kk];
                    acc[i][0] += xv * w.x;
                    acc[i][1] += xv * w.y;
                    acc[i][2] += xv * w.z;
                    acc[i][3] += xv * w.w;
                }
            }
        }
#pragma unroll
        for (int i = 0; i < 4; i++) {
            float4 v;
            v.x = fmaxf(acc[i][0], 0.f);
            v.y = fmaxf(acc[i][1], 0.f);
            v.z = fmaxf(acc[i][2], 0.f);
            v.w = fmaxf(acc[i][3], 0.f);
            *(float4*)&yb[(tr * 4 + i) * 68 + j] = v;
        }
        __syncthreads();

        // ---- GEMM2: out = Y @ W2 + b2 (+skip) ----
#pragma unroll
        for (int i = 0; i < 4; i++)
#pragma unroll
            for (int c = 0; c < 4; c++) acc[i][c] = b2s[j + c];
#pragma unroll
        for (int k = 0; k < 64; k += 4) {
            float4 xq[4];
#pragma unroll
            for (int i = 0; i < 4; i++)
                xq[i] = *(const float4*)&yb[(tr * 4 + i) * 68 + k];
#pragma unroll
            for (int kk = 0; kk < 4; kk++) {
                float4 w = *(const float4*)&W2s[(k + kk) * 64 + j];
#pragma unroll
                for (int i = 0; i < 4; i++) {
                    float xv = ((const float*)&xq[i])[kk];
                    acc[i][0] += xv * w.x;
                    acc[i][1] += xv * w.y;
                    acc[i][2] += xv * w.z;
                    acc[i][3] += xv * w.w;
                }
            }
        }
#pragma unroll
        for (int i = 0; i < 4; i++) {
            int node = base + tr * 4 + i;
            if (node < n) {
                float4 v = make_float4(acc[i][0], acc[i][1], acc[i][2], acc[i][3]);
                if (skip) {
                    float4 sk = *(const float4*)&skip[(size_t)node * 64 + j];
                    v.x += sk.x; v.y += sk.y; v.z += sk.z; v.w += sk.w;
                }
                *(float4*)&out[(size_t)node * 64 + j] = v;
            }
        }
        __syncthreads();
    }
}

// decode: out[n,2] = relu(h@Wd1+bd1)@Wd2+bd2
__global__ __launch_bounds__(512) void decode_kernel(const float* __restrict__ hin,
                                                     const float* __restrict__ W1,
                                                     const float* __restrict__ b1,
                                                     const float* __restrict__ W2,
                                                     const float* __restrict__ b2,
                                                     float* __restrict__ out, int n) {
    __shared__ __align__(16) float W1s[D * D];
    __shared__ __align__(16) float b1s[D];
    __shared__ __align__(16) float W2s[D * 2];
    __shared__ __align__(16) float b2s[4];
    __shared__ __align__(16) float inb[8][D];
    __shared__ __align__(16) float yb[8][D];
    int t = threadIdx.x;
    for (int i = t; i < D * D; i += 512) W1s[i] = W1[i];
    if (t < D) b1s[t] = b1[t];
    if (t < D * 2) W2s[t] = W2[t];
    if (t < 2) b2s[t] = b2[t];
    __syncthreads();
    int g = t >> 6, j = t & 63;
    for (long base = (long)blockIdx.x * 8; base < n; base += (long)gridDim.x * 8) {
        int node = (int)base + g;
        bool valid = node < n;
        if (valid) inb[g][j] = hin[(size_t)node * D + j];
        __syncthreads();
        if (valid) {
            float acc = b1s[j];
            const float4* h4 = (const float4*)&inb[g][0];
#pragma unroll
            for (int kk = 0; kk < 16; kk++) {
                float4 v = h4[kk];
                int k = kk * 4;
                acc += v.x * W1s[(k + 0) * D + j];
                acc += v.y * W1s[(k + 1) * D + j];
                acc += v.z * W1s[(k + 2) * D + j];
                acc += v.w * W1s[(k + 3) * D + j];
            }
            yb[g][j] = fmaxf(acc, 0.0f);
        }
        __syncthreads();
        if (valid && j < 2) {
            float acc = b2s[j];
#pragma unroll
            for (int k = 0; k < D; k++) acc += yb[g][k] * W2s[k * 2 + j];
            out[(size_t)node * 2 + j] = acc;
        }
        __syncthreads();
    }
}

// ---------------------------------------------------------------------------
static inline int mini(long a, long b) { return (int)(a < b ? a : b); }

template <int IN>
static constexpr size_t mlp2_smem() {
    return (size_t)(IN * 64 + 64 * 64 + 64 + 64 + 64 * (IN + 4) + 64 * 68) * sizeof(float);
}

extern "C" void kernel_launch(void* const* d_in, const int* in_sizes, int n_in,
                              void* d_out, int out_size) {
    const float* x   = (const float*)d_in[0];
    const float* We1 = (const float*)d_in[1];
    const float* be1 = (const float*)d_in[2];
    const float* We2 = (const float*)d_in[3];
    const float* be2 = (const float*)d_in[4];
    const float* Wm1 = (const float*)d_in[5];
    const float* bm1 = (const float*)d_in[6];
    const float* Wm2 = (const float*)d_in[7];
    const float* bm2 = (const float*)d_in[8];
    const float* Wn1 = (const float*)d_in[9];
    const float* bn1 = (const float*)d_in[10];
    const float* Wn2 = (const float*)d_in[11];
    const float* bn2 = (const float*)d_in[12];
    const float* Wd1 = (const float*)d_in[13];
    const float* bd1 = (const float*)d_in[14];
    const float* Wd2 = (const float*)d_in[15];
    const float* bd2 = (const float*)d_in[16];
    const int* s_f  = (const int*)d_in[17];
    const int* r_f  = (const int*)d_in[18];
    const int* s_ds = (const int*)d_in[19];
    const int* r_ds = (const int*)d_in[20];
    const int* s_p  = (const int*)d_in[21];
    const int* r_p  = (const int*)d_in[22];
    const int* s_us = (const int*)d_in[23];
    const int* r_us = (const int*)d_in[24];
    const int* uppool   = (const int*)d_in[25];
    const int* downpool = (const int*)d_in[26];

    int N   = in_sizes[0] / 16;
    int NP  = in_sizes[26];
    int E   = in_sizes[17];
    int EDS = in_sizes[19];
    int EP  = in_sizes[21];
    int EUS = in_sizes[23];
    float* out = (float*)d_out;

    float *A, *B, *C, *M, *AG;
    cudaGetSymbolAddress((void**)&A, g_A);
    cudaGetSymbolAddress((void**)&B, g_B);
    cudaGetSymbolAddress((void**)&C, g_C);
    cudaGetSymbolAddress((void**)&M, g_M);
    cudaGetSymbolAddress((void**)&AG, g_AG);

    static bool attr_done = false;
    if (!attr_done) {
        cudaFuncSetAttribute(mlp2_tiled<16>, cudaFuncAttributeMaxDynamicSharedMemorySize,
                             (int)mlp2_smem<16>());
        cudaFuncSetAttribute(mlp2_tiled<64>, cudaFuncAttributeMaxDynamicSharedMemorySize,
                             (int)mlp2_smem<64>());
        cudaFuncSetAttribute(mlp2_tiled<128>, cudaFuncAttributeMaxDynamicSharedMemorySize,
                             (int)mlp2_smem<128>());
        attr_done = true;
    }

    auto grid_for = [](int n) { return mini(((long)n + 63) / 64, 2048); };

    auto mp = [&](int l, const float* hin, float* hout, const int* s, const int* r,
                  int Ecnt, int n, const float* skip) {
        // per-node message MLP (messages depend only on sender features)
        mlp2_tiled<64><<<grid_for(n), 256, mlp2_smem<64>()>>>(
            hin, nullptr, Wm1 + (size_t)l * D * D, bm1 + (size_t)l * D,
            Wm2 + (size_t)l * D * D, bm2 + (size_t)l * D, nullptr, M, n);
        zero_kernel<<<(n * D + 511) / 512, 512>>>(AG, n * D);
        long E16 = (long)Ecnt * 16;
        scatter_kernel<<<mini((E16 + 255) / 256, 8192), 256>>>(M, s, r, AG, E16);
        // node MLP on [h | aggr]
        mlp2_tiled<128><<<grid_for(n), 256, mlp2_smem<128>()>>>(
            hin, AG, Wn1 + (size_t)l * 128 * D, bn1 + (size_t)l * D,
            Wn2 + (size_t)l * D * D, bn2 + (size_t)l * D, skip, hout, n);
    };

    // encode
    mlp2_tiled<16><<<grid_for(N), 256, mlp2_smem<16>()>>>(
        x, nullptr, We1, be1, We2, be2, nullptr, A, N);
    // two fine MP layers
    mp(0, A, B, s_f, r_f, E, N, nullptr);
    mp(1, B, C, s_f, r_f, E, N, nullptr);
    // skip = C
    // downsample path: gather by uppool, MP on downsampling graph
    gather_kernel<<<(N * 16 + 511) / 512, 512>>>(C, uppool, A, N);
    mp(2, A, B, s_ds, r_ds, EDS, N, nullptr);
    // select pooled nodes
    gather_kernel<<<(NP * 16 + 511) / 512, 512>>>(B, downpool, A, NP);
    // bottleneck
    mp(3, A, B, s_p, r_p, EP, NP, nullptr);
    mp(4, B, A, s_p, r_p, EP, NP, nullptr);
    // upsample path: gather by downpool, MP on upsampling graph
    gather_kernel<<<(NP * 16 + 511) / 512, 512>>>(A, downpool, B, NP);
    mp(5, B, A, s_us, r_us, EUS, NP, nullptr);
    // scatter back to fine level via uppool gather
    gather_kernel<<<(N * 16 + 511) / 512, 512>>>(A, uppool, B, N);
    // decode MP layers with skip connections
    mp(6, B, A, s_f, r_f, E, N, C);
    mp(7, A, B, s_f, r_f, E, N, C);
    // decode head
    decode_kernel<<<mini(((long)N + 7) / 8, 4096), 512>>>(B, Wd1, bd1, Wd2, bd2, out, N);
}

// round 4
// speedup vs baseline: 8.2570x; 1.1150x over previous
#include <cuda_runtime.h>
#include <cstddef>

#define D 64
#define MAXN 100000

// Scratch buffers (no allocation allowed) -----------------------------------
__device__ float g_A[MAXN * D];
__device__ float g_B[MAXN * D];
__device__ float g_C[MAXN * D];
__device__ float g_M[MAXN * D];   // per-node messages
__device__ float g_AG[MAXN * D];  // aggregation

// ---------------------------------------------------------------------------
// packed f32x2 helpers (sm_103a: fma.rn.f32x2 doubles fp32 FMA throughput)
__device__ __forceinline__ unsigned long long fma2(unsigned long long a,
                                                   unsigned long long b,
                                                   unsigned long long c) {
    unsigned long long d;
    asm("fma.rn.f32x2 %0, %1, %2, %3;" : "=l"(d) : "l"(a), "l"(b), "l"(c));
    return d;
}
__device__ __forceinline__ unsigned long long pk2(float lo, float hi) {
    unsigned long long r;
    asm("mov.b64 %0, {%1, %2};" : "=l"(r)
        : "r"(__float_as_uint(lo)), "r"(__float_as_uint(hi)));
    return r;
}
__device__ __forceinline__ float2 unpk(unsigned long long p) {
    unsigned int lo, hi;
    asm("mov.b64 {%0, %1}, %2;" : "=r"(lo), "=r"(hi) : "l"(p));
    return make_float2(__uint_as_float(lo), __uint_as_float(hi));
}
union F4U { float4 v; unsigned long long u[2]; };

// ---------------------------------------------------------------------------
__global__ __launch_bounds__(512) void zero_kernel(float4* __restrict__ p, int n4) {
    int i = blockIdx.x * blockDim.x + threadIdx.x;
    if (i < n4) p[i] = make_float4(0.f, 0.f, 0.f, 0.f);
}

// out[i,:] = in[idx[i],:]  (row width 64)
__global__ __launch_bounds__(512) void gather_kernel(const float* __restrict__ in,
                                                     const int* __restrict__ idx,
                                                     float* __restrict__ out, int n) {
    int i = blockIdx.x * blockDim.x + threadIdx.x;
    if (i < n * 16) {
        int row = i >> 4;
        int c = i & 15;
        ((float4*)out)[i] = ((const float4*)in)[(size_t)idx[row] * 16 + c];
    }
}

// aggr[r[e],:] += msg[s[e],:]   via red.global.add.v4.f32
__global__ __launch_bounds__(256) void scatter_kernel(const float* __restrict__ msg,
                                                      const int* __restrict__ s,
                                                      const int* __restrict__ r,
                                                      float* __restrict__ aggr, long E16) {
    for (long i = (long)blockIdx.x * 256 + threadIdx.x; i < E16;
         i += (long)gridDim.x * 256) {
        int e = (int)(i >> 4);
        int c = (int)(i & 15);
        int se = __ldg(&s[e]);
        int re = __ldg(&r[e]);
        float4 v = __ldg((const float4*)msg + (size_t)se * 16 + c);
        float* dst = aggr + (size_t)re * 64 + c * 4;
        asm volatile("red.global.add.v4.f32 [%0], {%1,%2,%3,%4};"
                     :: "l"(dst), "f"(v.x), "f"(v.y), "f"(v.z), "f"(v.w)
                     : "memory");
    }
}

// ---------------------------------------------------------------------------
// Register-tiled 2-layer MLP with packed f32x2 FMA.
// out[row] = relu(X[row] @ W1 + b1) @ W2 + b2 (+skip[row])
// X rows: [in0 | in1] when IN==128, else in0 (row width IN).
// If rowidx != null, X rows are in0/in1[rowidx[row]]; out rows compact.
// 256 threads; tile = 64 rows x 64 cols; thread tile = 4 rows x 4 cols.
// ---------------------------------------------------------------------------
template <int IN>
__global__ __launch_bounds__(256) void mlp2_tiled(const float* __restrict__ in0,
                                                  const float* __restrict__ in1,
                                                  const int* __restrict__ rowidx,
                                                  const float* __restrict__ W1,
                                                  const float* __restrict__ b1,
                                                  const float* __restrict__ W2,
                                                  const float* __restrict__ b2,
                                                  const float* __restrict__ skip,
                                                  float* __restrict__ out, int n) {
    extern __shared__ __align__(16) float sm[];
    constexpr int XS = IN + 4;               // padded input row stride (floats)
    float* W1s = sm;                         // IN*64
    float* W2s = W1s + IN * 64;              // 64*64
    float* b1s = W2s + 64 * 64;              // 64
    float* b2s = b1s + 64;                   // 64
    float* inb = b2s + 64;                   // 64*XS
    float* yb  = inb + 64 * XS;              // 64*68

    const int t = threadIdx.x;
    for (int i = t; i < IN * 64; i += 256) W1s[i] = W1[i];
    for (int i = t; i < 64 * 64; i += 256) W2s[i] = W2[i];
    if (t < 64) { b1s[t] = b1[t]; b2s[t] = b2[t]; }
    __syncthreads();

    const int tc = t & 15;        // col group (j = tc*4)
    const int tr = t >> 4;        // row group (rows tr*4 .. tr*4+3)
    const int j = tc * 4;
    const int tiles = (n + 63) >> 6;

    for (int tile = blockIdx.x; tile < tiles; tile += gridDim.x) {
        const int base = tile * 64;
        // ---- stage X tile ----
        constexpr int C4 = IN / 4;
        for (int i = t; i < 64 * C4; i += 256) {
            int row = i / C4, c4 = i % C4, col = c4 * 4;
            int node = base + row;
            float4 v = make_float4(0.f, 0.f, 0.f, 0.f);
            if (node < n) {
                int src = rowidx ? rowidx[node] : node;
                if (IN == 128 && col >= 64)
                    v = *(const float4*)&in1[(size_t)src * 64 + (col - 64)];
                else
                    v = *(const float4*)&in0[(size_t)src * (IN == 128 ? 64 : IN) + col];
            }
            *(float4*)&inb[row * XS + col] = v;
        }
        __syncthreads();

        // ---- GEMM1: Y = relu(X @ W1 + b1) ----
        unsigned long long a0[4], a1[4];
        {
            unsigned long long bi0 = pk2(b1s[j], b1s[j + 1]);
            unsigned long long bi1 = pk2(b1s[j + 2], b1s[j + 3]);
#pragma unroll
            for (int i = 0; i < 4; i++) { a0[i] = bi0; a1[i] = bi1; }
        }
#pragma unroll
        for (int k = 0; k < IN; k += 4) {
            float4 xq[4];
#pragma unroll
            for (int i = 0; i < 4; i++)
                xq[i] = *(const float4*)&inb[(tr * 4 + i) * XS + k];
#pragma unroll
            for (int kk = 0; kk < 4; kk++) {
                F4U w; w.v = *(const float4*)&W1s[(k + kk) * 64 + j];
#pragma unroll
                for (int i = 0; i < 4; i++) {
                    float xv = ((const float*)&xq[i])[kk];
                    unsigned long long xp = pk2(xv, xv);
                    a0[i] = fma2(xp, w.u[0], a0[i]);
                    a1[i] = fma2(xp, w.u[1], a1[i]);
                }
            }
        }
#pragma unroll
        for (int i = 0; i < 4; i++) {
            float2 lo = unpk(a0[i]), hi = unpk(a1[i]);
            float4 v;
            v.x = fmaxf(lo.x, 0.f); v.y = fmaxf(lo.y, 0.f);
            v.z = fmaxf(hi.x, 0.f); v.w = fmaxf(hi.y, 0.f);
            *(float4*)&yb[(tr * 4 + i) * 68 + j] = v;
        }
        __syncthreads();

        // ---- GEMM2: out = Y @ W2 + b2 (+skip) ----
        {
            unsigned long long bi0 = pk2(b2s[j], b2s[j + 1]);
            unsigned long long bi1 = pk2(b2s[j + 2], b2s[j + 3]);
#pragma unroll
            for (int i = 0; i < 4; i++) { a0[i] = bi0; a1[i] = bi1; }
        }
#pragma unroll
        for (int k = 0; k < 64; k += 4) {
            float4 xq[4];
#pragma unroll
            for (int i = 0; i < 4; i++)
                xq[i] = *(const float4*)&yb[(tr * 4 + i) * 68 + k];
#pragma unroll
            for (int kk = 0; kk < 4; kk++) {
                F4U w; w.v = *(const float4*)&W2s[(k + kk) * 64 + j];
#pragma unroll
                for (int i = 0; i < 4; i++) {
                    float xv = ((const float*)&xq[i])[kk];
                    unsigned long long xp = pk2(xv, xv);
                    a0[i] = fma2(xp, w.u[0], a0[i]);
                    a1[i] = fma2(xp, w.u[1], a1[i]);
                }
            }
        }
#pragma unroll
        for (int i = 0; i < 4; i++) {
            int node = base + tr * 4 + i;
            if (node < n) {
                float2 lo = unpk(a0[i]), hi = unpk(a1[i]);
                float4 v = make_float4(lo.x, lo.y, hi.x, hi.y);
                if (skip) {
                    float4 sk = *(const float4*)&skip[(size_t)node * 64 + j];
                    v.x += sk.x; v.y += sk.y; v.z += sk.z; v.w += sk.w;
                }
                *(float4*)&out[(size_t)node * 64 + j] = v;
            }
        }
        __syncthreads();
    }
}

// decode: out[n,2] = relu(h@Wd1+bd1)@Wd2+bd2
__global__ __launch_bounds__(512) void decode_kernel(const float* __restrict__ hin,
                                                     const float* __restrict__ W1,
                                                     const float* __restrict__ b1,
                                                     const float* __restrict__ W2,
                                                     const float* __restrict__ b2,
                                                     float* __restrict__ out, int n) {
    __shared__ __align__(16) float W1s[D * D];
    __shared__ __align__(16) float b1s[D];
    __shared__ __align__(16) float W2s[D * 2];
    __shared__ __align__(16) float b2s[4];
    __shared__ __align__(16) float inb[8][D];
    __shared__ __align__(16) float yb[8][D];
    int t = threadIdx.x;
    for (int i = t; i < D * D; i += 512) W1s[i] = W1[i];
    if (t < D) b1s[t] = b1[t];
    if (t < D * 2) W2s[t] = W2[t];
    if (t < 2) b2s[t] = b2[t];
    __syncthreads();
    int g = t >> 6, j = t & 63;
    for (long base = (long)blockIdx.x * 8; base < n; base += (long)gridDim.x * 8) {
        int node = (int)base + g;
        bool valid = node < n;
        if (valid) inb[g][j] = hin[(size_t)node * D + j];
        __syncthreads();
        if (valid) {
            float acc = b1s[j];
            const float4* h4 = (const float4*)&inb[g][0];
#pragma unroll
            for (int kk = 0; kk < 16; kk++) {
                float4 v = h4[kk];
                int k = kk * 4;
                acc += v.x * W1s[(k + 0) * D + j];
                acc += v.y * W1s[(k + 1) * D + j];
                acc += v.z * W1s[(k + 2) * D + j];
                acc += v.w * W1s[(k + 3) * D + j];
            }
            yb[g][j] = fmaxf(acc, 0.0f);
        }
        __syncthreads();
        if (valid && j < 2) {
            float acc = b2s[j];
#pragma unroll
            for (int k = 0; k < D; k++) acc += yb[g][k] * W2s[k * 2 + j];
            out[(size_t)node * 2 + j] = acc;
        }
        __syncthreads();
    }
}

// ---------------------------------------------------------------------------
static inline int mini(long a, long b) { return (int)(a < b ? a : b); }

template <int IN>
static constexpr size_t mlp2_smem() {
    return (size_t)(IN * 64 + 64 * 64 + 64 + 64 + 64 * (IN + 4) + 64 * 68) * sizeof(float);
}

extern "C" void kernel_launch(void* const* d_in, const int* in_sizes, int n_in,
                              void* d_out, int out_size) {
    const float* x   = (const float*)d_in[0];
    const float* We1 = (const float*)d_in[1];
    const float* be1 = (const float*)d_in[2];
    const float* We2 = (const float*)d_in[3];
    const float* be2 = (const float*)d_in[4];
    const float* Wm1 = (const float*)d_in[5];
    const float* bm1 = (const float*)d_in[6];
    const float* Wm2 = (const float*)d_in[7];
    const float* bm2 = (const float*)d_in[8];
    const float* Wn1 = (const float*)d_in[9];
    const float* bn1 = (const float*)d_in[10];
    const float* Wn2 = (const float*)d_in[11];
    const float* bn2 = (const float*)d_in[12];
    const float* Wd1 = (const float*)d_in[13];
    const float* bd1 = (const float*)d_in[14];
    const float* Wd2 = (const float*)d_in[15];
    const float* bd2 = (const float*)d_in[16];
    const int* s_f  = (const int*)d_in[17];
    const int* r_f  = (const int*)d_in[18];
    const int* s_ds = (const int*)d_in[19];
    const int* r_ds = (const int*)d_in[20];
    const int* s_p  = (const int*)d_in[21];
    const int* r_p  = (const int*)d_in[22];
    const int* s_us = (const int*)d_in[23];
    const int* r_us = (const int*)d_in[24];
    const int* uppool   = (const int*)d_in[25];
    const int* downpool = (const int*)d_in[26];

    int N   = in_sizes[0] / 16;
    int NP  = in_sizes[26];
    int E   = in_sizes[17];
    int EDS = in_sizes[19];
    int EP  = in_sizes[21];
    int EUS = in_sizes[23];
    float* out = (float*)d_out;

    float *A, *B, *C, *M, *AG;
    cudaGetSymbolAddress((void**)&A, g_A);
    cudaGetSymbolAddress((void**)&B, g_B);
    cudaGetSymbolAddress((void**)&C, g_C);
    cudaGetSymbolAddress((void**)&M, g_M);
    cudaGetSymbolAddress((void**)&AG, g_AG);

    static bool attr_done = false;
    if (!attr_done) {
        cudaFuncSetAttribute(mlp2_tiled<16>, cudaFuncAttributeMaxDynamicSharedMemorySize,
                             (int)mlp2_smem<16>());
        cudaFuncSetAttribute(mlp2_tiled<64>, cudaFuncAttributeMaxDynamicSharedMemorySize,
                             (int)mlp2_smem<64>());
        cudaFuncSetAttribute(mlp2_tiled<128>, cudaFuncAttributeMaxDynamicSharedMemorySize,
                             (int)mlp2_smem<128>());
        attr_done = true;
    }

    auto grid_for = [](int n) { return mini(((long)n + 63) / 64, 2048); };

    // one message-passing layer; node MLP optionally restricted to sel rows
    auto mp = [&](int l, const float* hin, float* hout, const int* s, const int* r,
                  int Ecnt, int n, const float* skip, const int* sel, int nout) {
        mlp2_tiled<64><<<grid_for(n), 256, mlp2_smem<64>()>>>(
            hin, nullptr, nullptr, Wm1 + (size_t)l * D * D, bm1 + (size_t)l * D,
            Wm2 + (size_t)l * D * D, bm2 + (size_t)l * D, nullptr, M, n);
        zero_kernel<<<(n * 16 + 511) / 512, 512>>>((float4*)AG, n * 16);
        long E16 = (long)Ecnt * 16;
        scatter_kernel<<<mini((E16 + 255) / 256, 8192), 256>>>(M, s, r, AG, E16);
        mlp2_tiled<128><<<grid_for(nout), 256, mlp2_smem<128>()>>>(
            hin, AG, sel, Wn1 + (size_t)l * 128 * D, bn1 + (size_t)l * D,
            Wn2 + (size_t)l * D * D, bn2 + (size_t)l * D, skip, hout, nout);
    };

    // encode
    mlp2_tiled<16><<<grid_for(N), 256, mlp2_smem<16>()>>>(
        x, nullptr, nullptr, We1, be1, We2, be2, nullptr, A, N);
    // two fine MP layers
    mp(0, A, B, s_f, r_f, E, N, nullptr, nullptr, N);
    mp(1, B, C, s_f, r_f, E, N, nullptr, nullptr, N);
    // skip = C
    // downsample: gather h[uppool], MP on ds graph, node MLP only on downpool rows
    gather_kernel<<<(N * 16 + 511) / 512, 512>>>(C, uppool, A, N);
    mp(2, A, B, s_ds, r_ds, EDS, N, nullptr, downpool, NP);   // B = hp [NP]
    // bottleneck
    mp(3, B, A, s_p, r_p, EP, NP, nullptr, nullptr, NP);
    mp(4, A, B, s_p, r_p, EP, NP, nullptr, nullptr, NP);
    // upsample path: gather by downpool, MP on upsampling graph
    gather_kernel<<<(NP * 16 + 511) / 512, 512>>>(B, downpool, A, NP);
    mp(5, A, B, s_us, r_us, EUS, NP, nullptr, nullptr, NP);
    // scatter back to fine level via uppool gather
    gather_kernel<<<(N * 16 + 511) / 512, 512>>>(B, uppool, A, N);
    // decode MP layers with skip connections
    mp(6, A, B, s_f, r_f, E, N, C, nullptr, N);
    mp(7, B, A, s_f, r_f, E, N, C, nullptr, N);
    // decode head
    decode_kernel<<<mini(((long)N + 7) / 8, 4096), 512>>>(A, Wd1, bd1, Wd2, bd2, out, N);
}